// round 1
// baseline (speedup 1.0000x reference)
#include <cuda_runtime.h>
#include <cuda_bf16.h>
#include <math.h>

// Shapes (fixed by the problem)
#define BATCH   32
#define CIN     512
#define HW      196            // 14*14
#define DPROJ   8192
#define DMASK   8191

// Gram/scatter tiling
#define CH      128            // c-chunk per CTA tile (4 chunks -> 512)
#define KT      49             // K tile (4*49 = 196)
#define XS      132            // smem row stride (floats), mult of 4 for LDS.128
#define NTHR    256

typedef unsigned long long ull;

// ---- device scratch (no allocations allowed) ----
__device__ int   d_h[2][CIN];
__device__ float d_s[2][CIN];
__device__ float d_yacc[BATCH * DPROJ];

// ---- packed f32x2 helpers (sm_100+: FFMA2 only reachable via PTX) ----
__device__ __forceinline__ ull pack2(float x, float y) {
    ull r; asm("mov.b64 %0, {%1, %2};" : "=l"(r) : "f"(x), "f"(y)); return r;
}
__device__ __forceinline__ void unpack2(ull v, float& x, float& y) {
    asm("mov.b64 {%0, %1}, %2;" : "=f"(x), "=f"(y) : "l"(v));
}
__device__ __forceinline__ ull ffma2(ull a, ull b, ull c) {
    ull d; asm("fma.rn.f32x2 %0, %1, %2, %3;" : "=l"(d) : "l"(a), "l"(b), "l"(c));
    return d;
}

// ============================================================
// Kernel 1: extract count-sketch (h, s) from dense S1/S2.
// One warp per row; each row has exactly one nonzero (+-1).
// ============================================================
__global__ void extract_kernel(const float* __restrict__ S1,
                               const float* __restrict__ S2) {
    int wg   = (blockIdx.x << 3) + (threadIdx.x >> 5);   // 128 blocks * 8 warps = 1024
    int lane = threadIdx.x & 31;
    int m = wg >> 9;          // 0 -> S1, 1 -> S2
    int r = wg & 511;
    const float4* S4 = (const float4*)((m ? S2 : S1) + (size_t)r * DPROJ);
    for (int i = lane; i < DPROJ / 4; i += 32) {
        float4 v = S4[i];
        int base = i << 2;
        if (v.x != 0.f) { d_h[m][r] = base + 0; d_s[m][r] = v.x; }
        if (v.y != 0.f) { d_h[m][r] = base + 1; d_s[m][r] = v.y; }
        if (v.z != 0.f) { d_h[m][r] = base + 2; d_s[m][r] = v.z; }
        if (v.w != 0.f) { d_h[m][r] = base + 3; d_s[m][r] = v.w; }
    }
}

// ============================================================
// Kernel 2: zero the global accumulator (graph is replayed).
// ============================================================
__global__ void zero_kernel() {
    float4* p = (float4*)d_yacc;
    p[blockIdx.x * blockDim.x + threadIdx.x] = make_float4(0.f, 0.f, 0.f, 0.f);
}

// ============================================================
// Kernel 3: fused Gram tile + count-sketch-conv scatter.
// grid = (16 tiles, 32 images). Tile = 128x128 of G, thread = 8x8.
// Signs s1/s2 are folded into the operand tiles at load time, so
// the scatter is:  bins[(h1[c1]+h2[c2]) & 8191] += G~[c1,c2].
// ============================================================
__global__ __launch_bounds__(NTHR, 2)
void gram_scatter(const float* __restrict__ x) {
    extern __shared__ float sm[];
    float* bins = sm;                         // DPROJ floats
    float* As   = sm + DPROJ;                 // KT * XS
    float* Bs   = As + KT * XS;               // KT * XS

    const int b    = blockIdx.y;
    const int tile = blockIdx.x;
    const int c1_0 = (tile >> 2) * CH;
    const int c2_0 = (tile & 3)  * CH;
    const int tid  = threadIdx.x;
    const int ti   = tid >> 4;                // 0..15
    const int tj   = tid & 15;                // 0..15
    const int ao   = ti * 8;
    const int bo   = tj * 8;

    for (int l = tid; l < DPROJ; l += NTHR) bins[l] = 0.f;

    const float* xb = x + (size_t)b * CIN * HW;

    ull acc[8][4];
#pragma unroll
    for (int i = 0; i < 8; ++i)
#pragma unroll
        for (int j = 0; j < 4; ++j) acc[i][j] = 0ULL;

    for (int kt = 0; kt < 4; ++kt) {
        const int k0 = kt * KT;
        __syncthreads();   // protects bins zeroing (kt==0) / prev compute (kt>0)
        for (int l = tid; l < CH * KT; l += NTHR) {
            int ci = l / KT;
            int k  = l - ci * KT;
            As[k * XS + ci] = xb[(c1_0 + ci) * HW + k0 + k] * d_s[0][c1_0 + ci];
            Bs[k * XS + ci] = xb[(c2_0 + ci) * HW + k0 + k] * d_s[1][c2_0 + ci];
        }
        __syncthreads();

        for (int k = 0; k < KT; ++k) {
            const float* Ar = As + k * XS + ao;
            float4 a0 = *(const float4*)(Ar);
            float4 a1 = *(const float4*)(Ar + 4);
            ull ap[8];
            ap[0] = pack2(a0.x, a0.x); ap[1] = pack2(a0.y, a0.y);
            ap[2] = pack2(a0.z, a0.z); ap[3] = pack2(a0.w, a0.w);
            ap[4] = pack2(a1.x, a1.x); ap[5] = pack2(a1.y, a1.y);
            ap[6] = pack2(a1.z, a1.z); ap[7] = pack2(a1.w, a1.w);

            const float* Br = Bs + k * XS + bo;
            ulonglong2 bb0 = *(const ulonglong2*)(Br);       // pairs (b0,b1),(b2,b3)
            ulonglong2 bb1 = *(const ulonglong2*)(Br + 4);   // pairs (b4,b5),(b6,b7)
#pragma unroll
            for (int i = 0; i < 8; ++i) {
                acc[i][0] = ffma2(ap[i], bb0.x, acc[i][0]);
                acc[i][1] = ffma2(ap[i], bb0.y, acc[i][1]);
                acc[i][2] = ffma2(ap[i], bb1.x, acc[i][2]);
                acc[i][3] = ffma2(ap[i], bb1.y, acc[i][3]);
            }
        }
    }
    __syncthreads();   // all FMA traffic done before heavy bin atomics phase

    // Scatter this thread's 8x8 tile into the shared bins.
    int h1r[8], h2r[8];
#pragma unroll
    for (int i = 0; i < 8; ++i) h1r[i] = d_h[0][c1_0 + ao + i];
#pragma unroll
    for (int j = 0; j < 8; ++j) h2r[j] = d_h[1][c2_0 + bo + j];

#pragma unroll
    for (int i = 0; i < 8; ++i) {
#pragma unroll
        for (int jp = 0; jp < 4; ++jp) {
            float g0, g1;
            unpack2(acc[i][jp], g0, g1);
            atomicAdd(&bins[(h1r[i] + h2r[2 * jp + 0]) & DMASK], g0);
            atomicAdd(&bins[(h1r[i] + h2r[2 * jp + 1]) & DMASK], g1);
        }
    }
    __syncthreads();

    // Merge local bins into the per-image global accumulator.
    float* yb = d_yacc + (size_t)b * DPROJ;
    for (int l = tid; l < DPROJ; l += NTHR) {
        float v = bins[l];
        if (v != 0.f) atomicAdd(&yb[l], v);
    }
}

// ============================================================
// Kernel 4: signed sqrt + L2 normalize per image row.
// ============================================================
__global__ void finalize_kernel(float* __restrict__ out) {
    __shared__ float red[8];
    const int b   = blockIdx.x;
    const int tid = threadIdx.x;
    const float* yb = d_yacc + (size_t)b * DPROJ;
    float* ob = out + (size_t)b * DPROJ;

    float ss = 0.f;
    for (int l = tid; l < DPROJ; l += NTHR) {
        float v = yb[l];
        float t;
        if      (v > 0.f) t =  sqrtf( v + 1e-8f);
        else if (v < 0.f) t = -sqrtf(-v + 1e-8f);
        else              t = 0.f;
        ob[l] = t;
        ss += t * t;
    }
#pragma unroll
    for (int o = 16; o; o >>= 1) ss += __shfl_xor_sync(0xFFFFFFFFu, ss, o);
    if ((tid & 31) == 0) red[tid >> 5] = ss;
    __syncthreads();
    if (tid == 0) {
        float s = 0.f;
        for (int i = 0; i < 8; ++i) s += red[i];
        float norm = sqrtf(s);
        red[0] = 1.f / fmaxf(norm, 1e-12f);
    }
    __syncthreads();
    float inv = red[0];
    for (int l = tid; l < DPROJ; l += NTHR) ob[l] *= inv;
}

// ============================================================
extern "C" void kernel_launch(void* const* d_in, const int* in_sizes, int n_in,
                              void* d_out, int out_size) {
    (void)in_sizes; (void)n_in; (void)out_size;
    const float* x  = (const float*)d_in[0];
    const float* S1 = (const float*)d_in[1];
    const float* S2 = (const float*)d_in[2];
    float* out = (float*)d_out;

    const int smem_bytes = (DPROJ + 2 * KT * XS) * (int)sizeof(float);  // 84512
    cudaFuncSetAttribute(gram_scatter,
                         cudaFuncAttributeMaxDynamicSharedMemorySize, smem_bytes);

    extract_kernel<<<128, 256>>>(S1, S2);
    zero_kernel<<<(BATCH * DPROJ / 4) / 256, 256>>>();
    gram_scatter<<<dim3(16, BATCH), NTHR, smem_bytes>>>(x);
    finalize_kernel<<<BATCH, NTHR>>>(out);
}